// round 8
// baseline (speedup 1.0000x reference)
#include <cuda_runtime.h>

// ProbsNet fused single-kernel, cp.async (LDGSTS) smem pipeline, 4 stages.
//   out = sum_i c0[i]*tmp0[i] + c1[i]*tmp1[i]
//   tmpX[i] = sum_d sigmoid(pB*(pBEV*BEV + STX[i,d])) * WX[i,d]
// 176 MB fp32 read-once streaming. Register pipelines (R6/R7) plateaued at
// DRAM~68% because load issue is coupled to the MUFU-heavy compute via the
// register scoreboard. cp.async decouples: loads stream into smem stages,
// compute consumes each thread's own slot (no block sync needed in loop).

#define D        131072
#define NROWS    84
#define VPR      (D / 4)              // 32768 float4 per row
#define NVEC     (NROWS * VPR)        // 2752512 float4 per (ST,W) pair
#define BLOCK    256
#define TILEV    256                  // float4 per array per tile (1/thread)
#define TILES1   (NVEC / TILEV)       // 10752 tiles per pair (exact)
#define TILES    (2 * TILES1)         // 21504
#define STAGES   4
#define GRID     888                  // 148 SMs * 6 blocks (smem-limited)

__device__ float        g_part[GRID];
__device__ unsigned int g_sem = 0;    // self-resetting (graph-replay safe)

// --- cp.async helpers ---
__device__ __forceinline__ void cp16(void* dst_smem, const void* src_gmem) {
    unsigned s = (unsigned)__cvta_generic_to_shared(dst_smem);
    asm volatile("cp.async.cg.shared.global [%0], [%1], 16;\n"
                 :: "r"(s), "l"(src_gmem));
}
#define CP_COMMIT() asm volatile("cp.async.commit_group;\n" ::: "memory")
#define CP_WAIT(n)  asm volatile("cp.async.wait_group %0;\n" :: "n"(n) : "memory")

// Entry e (0..83) of calc_probs(logits), flattened (4,21) layout.
__device__ __forceinline__ float probs_entry(const float* __restrict__ logits, int e) {
    float e0 = __expf(logits[0]);
    float e1 = __expf(logits[1]);
    float e2 = __expf(logits[2]);
    float e3 = __expf(logits[3]);
    float inv = __fdividef(1.0f, e0 + e1 + e2 + e3);
    float p[4] = {e0 * inv, e1 * inv, e2 * inv, e3 * inv};
    int i = e / 21;
    int r = e - i * 21;
    float v = p[i];
    if (r > 0) {
        int q  = r - 1;
        int j  = q / 5;
        int rr = q - j * 5;
        v *= p[j];
        if (rr > 0) v *= p[rr - 1];
    }
    return v;
}

// sigmoid(pB*(bev+s)) = 1/(1+exp2(a*s+b)), a=-pB*log2e, b=a*bev.
__device__ __forceinline__ float sig_dot4(float4 s4, float4 w4, float a, float b) {
    float t;
    t  = w4.x * __fdividef(1.0f, 1.0f + exp2f(fmaf(a, s4.x, b)));
    t += w4.y * __fdividef(1.0f, 1.0f + exp2f(fmaf(a, s4.y, b)));
    t += w4.z * __fdividef(1.0f, 1.0f + exp2f(fmaf(a, s4.z, b)));
    t += w4.w * __fdividef(1.0f, 1.0f + exp2f(fmaf(a, s4.w, b)));
    return t;
}

__global__ void __launch_bounds__(BLOCK)
fused_kernel(const float* __restrict__ BEV,
             const float* __restrict__ ST0, const float* __restrict__ W0,
             const float* __restrict__ ST1, const float* __restrict__ W1,
             const float* __restrict__ probs0, const float* __restrict__ probs1,
             const float* __restrict__ probs2, const float* __restrict__ probs3,
             const float* __restrict__ probs4,
             const float* __restrict__ pBEV, const float* __restrict__ pB,
             float* __restrict__ out) {
    __shared__ float4 s_st[STAGES][BLOCK];   // 16 KB
    __shared__ float4 s_w [STAGES][BLOCK];   // 16 KB
    __shared__ float  sc[2 * NROWS];
    __shared__ float  sm[BLOCK / 32];

    const int tid = threadIdx.x;
    const int bid = blockIdx.x;

    if (tid < NROWS) {
        sc[tid] = 0.2f * probs_entry(probs0, tid);
        float c1 = probs_entry(probs1, tid) + probs_entry(probs2, tid)
                 + probs_entry(probs3, tid) + probs_entry(probs4, tid);
        sc[NROWS + tid] = 0.2f * c1;
    }

    const float4* __restrict__ st0 = (const float4*)ST0;
    const float4* __restrict__ w0  = (const float4*)W0;
    const float4* __restrict__ st1 = (const float4*)ST1;
    const float4* __restrict__ w1  = (const float4*)W1;

    // Issue one pipeline stage for global tile t into buffer s.
    // Always commits exactly one group (possibly empty) to keep counts sane.
    auto issue_stage = [&](int s, int t) {
        if (t < TILES) {
            const bool second = (t >= TILES1);
            const int  ti     = second ? (t - TILES1) : t;
            const float4* __restrict__ st = second ? st1 : st0;
            const float4* __restrict__ w  = second ? w1  : w0;
            const int v = ti * TILEV + tid;
            cp16(&s_st[s][tid], &st[v]);
            cp16(&s_w[s][tid],  &w[v]);
        }
        CP_COMMIT();
    };

    // Prologue: fill STAGES-1 stages.
    #pragma unroll
    for (int k = 0; k < STAGES - 1; k++)
        issue_stage(k, bid + k * GRID);

    __syncthreads();   // sc[] ready (placed after prologue to overlap)

    const float a = -pB[0] * 1.4426950408889634f;   // -pB * log2(e)
    const float b = a * (pBEV[0] * BEV[0]);

    const int nIter = (TILES - 1 - bid) / GRID + 1;  // bid < GRID <= TILES
    float acc = 0.0f;

    for (int i = 0; i < nIter; i++) {
        CP_WAIT(STAGES - 2);                 // group i complete
        const int buf = i & (STAGES - 1);
        const int t   = bid + i * GRID;

        const bool second = (t >= TILES1);
        const int  ti     = second ? (t - TILES1) : t;
        const float c = sc[(second ? NROWS : 0) + (ti >> 7)];  // ti*256/32768

        float4 s4 = s_st[buf][tid];
        float4 w4 = s_w[buf][tid];
        acc = fmaf(c, sig_dot4(s4, w4, a, b), acc);

        // Refill the buffer freed two iterations ago with tile i+STAGES-1.
        issue_stage((i + STAGES - 1) & (STAGES - 1), bid + (i + STAGES - 1) * GRID);
    }

    // --- block reduce (fixed tree, deterministic) ---
    for (int off = 16; off > 0; off >>= 1)
        acc += __shfl_down_sync(0xFFFFFFFFu, acc, off);

    int lane = tid & 31;
    int wid  = tid >> 5;
    if (lane == 0) sm[wid] = acc;
    __syncthreads();
    if (wid == 0) {
        float bsum = (lane < BLOCK / 32) ? sm[lane] : 0.0f;
        for (int off = 4; off > 0; off >>= 1)
            bsum += __shfl_down_sync(0xFFFFFFFFu, bsum, off);
        if (lane == 0) g_part[blockIdx.x] = bsum;
    }

    // --- last block folds partials (deterministic fixed-order) ---
    __shared__ bool is_last;
    __threadfence();
    if (tid == 0)
        is_last = (atomicAdd(&g_sem, 1u) == GRID - 1);
    __syncthreads();

    if (is_last) {
        __threadfence();
        float a2 = 0.0f;
        for (int i = tid; i < GRID; i += BLOCK)
            a2 += g_part[i];
        for (int off = 16; off > 0; off >>= 1)
            a2 += __shfl_down_sync(0xFFFFFFFFu, a2, off);
        if (lane == 0) sm[wid] = a2;
        __syncthreads();
        if (tid == 0) {
            float s = 0.0f;
            #pragma unroll
            for (int i = 0; i < BLOCK / 32; i++) s += sm[i];
            out[0] = s;
            g_sem  = 0;
        }
    }
}

// Input order: BEV, ST0, Weight0, ST1, Weight1, Problem, probs0..4, pBEV, pB
extern "C" void kernel_launch(void* const* d_in, const int* in_sizes, int n_in,
                              void* d_out, int out_size) {
    const float* BEV    = (const float*)d_in[0];
    const float* ST0    = (const float*)d_in[1];
    const float* W0     = (const float*)d_in[2];
    const float* ST1    = (const float*)d_in[3];
    const float* W1     = (const float*)d_in[4];
    const float* probs0 = (const float*)d_in[6];
    const float* probs1 = (const float*)d_in[7];
    const float* probs2 = (const float*)d_in[8];
    const float* probs3 = (const float*)d_in[9];
    const float* probs4 = (const float*)d_in[10];
    const float* pBEV   = (const float*)d_in[11];
    const float* pB     = (const float*)d_in[12];

    fused_kernel<<<GRID, BLOCK>>>(BEV, ST0, W0, ST1, W1,
                                  probs0, probs1, probs2, probs3, probs4,
                                  pBEV, pB, (float*)d_out);
}

// round 9
// speedup vs baseline: 1.0611x; 1.0611x over previous
#include <cuda_runtime.h>

// ProbsNet fused single-kernel: 3-stage register pipeline (prefetch dist 2)
// + MUFU.TANH sigmoid.
//   out = sum_i c0[i]*tmp0[i] + c1[i]*tmp1[i]
//   tmpX[i] = sum_d sigmoid(pB*(pBEV*BEV + STX[i,d])) * WX[i,d]
// sigmoid(x) = 0.5*tanh(0.5x)+0.5  ->  FFMA + MUFU.TANH + FFMA + FFMA.
// 176 MB fp32 read-once streaming. R6 (dist-1) hit DRAM 69%: loads for t+1
// only got one ~200cyc compute window vs ~380cyc DRAM latency. Distance 2
// gives ~400cyc coverage; tanh halves MUFU pressure and the dep chain.

#define D        131072
#define NROWS    84
#define VPR      (D / 4)              // 32768 float4 per row
#define NVEC     (NROWS * VPR)        // 2752512 float4 per (ST,W) pair
#define BLOCK    256
#define UNROLL   2
#define TILE     (BLOCK * UNROLL)     // 512 float4 per tile
#define TILES1   (NVEC / TILE)        // 5376 tiles per pair (exact, 64/row)
#define TILES    (2 * TILES1)         // 10752
#define GRID     444                  // 148 SMs * 3 blocks (84-reg budget)

__device__ float        g_part[GRID];
__device__ unsigned int g_sem = 0;    // self-resetting (graph-replay safe)

// Entry e (0..83) of calc_probs(logits), flattened (4,21) layout.
__device__ __forceinline__ float probs_entry(const float* __restrict__ logits, int e) {
    float e0 = __expf(logits[0]);
    float e1 = __expf(logits[1]);
    float e2 = __expf(logits[2]);
    float e3 = __expf(logits[3]);
    float inv = __fdividef(1.0f, e0 + e1 + e2 + e3);
    float p[4] = {e0 * inv, e1 * inv, e2 * inv, e3 * inv};
    int i = e / 21;
    int r = e - i * 21;
    float v = p[i];
    if (r > 0) {
        int q  = r - 1;
        int j  = q / 5;
        int rr = q - j * 5;
        v *= p[j];
        if (rr > 0) v *= p[rr - 1];
    }
    return v;
}

__device__ __forceinline__ float tanh_fast(float x) {
    float y;
    asm("tanh.approx.f32 %0, %1;" : "=f"(y) : "f"(x));
    return y;
}

// sigmoid(pB*(bev+s)) = 0.5*tanh(a*s+b)+0.5,  a = 0.5*pB, b = a*bev
__device__ __forceinline__ float sig_dot4(float4 s4, float4 w4, float a, float b) {
    float t;
    t  = w4.x * fmaf(0.5f, tanh_fast(fmaf(a, s4.x, b)), 0.5f);
    t = fmaf(w4.y, fmaf(0.5f, tanh_fast(fmaf(a, s4.y, b)), 0.5f), t);
    t = fmaf(w4.z, fmaf(0.5f, tanh_fast(fmaf(a, s4.z, b)), 0.5f), t);
    t = fmaf(w4.w, fmaf(0.5f, tanh_fast(fmaf(a, s4.w, b)), 0.5f), t);
    return t;
}

struct TileRegs {
    float4 s0, s1, w0, w1;
    float  c;
};

__device__ __forceinline__ void load_tile(
        TileRegs& r, int t, int tid,
        const float4* __restrict__ st0, const float4* __restrict__ w0,
        const float4* __restrict__ st1, const float4* __restrict__ w1,
        const float* __restrict__ sc) {
    const bool second = (t >= TILES1);
    const int  ti     = second ? (t - TILES1) : t;
    const int  v0     = ti * TILE;
    const float4* __restrict__ st = second ? st1 : st0;
    const float4* __restrict__ w  = second ? w1  : w0;
    r.c  = sc[(second ? NROWS : 0) + (v0 >> 15)];
    r.s0 = st[v0 + tid];
    r.s1 = st[v0 + BLOCK + tid];
    r.w0 = w[v0 + tid];
    r.w1 = w[v0 + BLOCK + tid];
}

__device__ __forceinline__ float compute_tile(const TileRegs& r, float a, float b) {
    return r.c * (sig_dot4(r.s0, r.w0, a, b) + sig_dot4(r.s1, r.w1, a, b));
}

__global__ void __launch_bounds__(BLOCK, 3)
fused_kernel(const float* __restrict__ BEV,
             const float* __restrict__ ST0, const float* __restrict__ W0,
             const float* __restrict__ ST1, const float* __restrict__ W1,
             const float* __restrict__ probs0, const float* __restrict__ probs1,
             const float* __restrict__ probs2, const float* __restrict__ probs3,
             const float* __restrict__ probs4,
             const float* __restrict__ pBEV, const float* __restrict__ pB,
             float* __restrict__ out) {
    __shared__ float sc[2 * NROWS];
    const int tid = threadIdx.x;

    if (tid < NROWS) {
        sc[tid] = 0.2f * probs_entry(probs0, tid);
        float c1 = probs_entry(probs1, tid) + probs_entry(probs2, tid)
                 + probs_entry(probs3, tid) + probs_entry(probs4, tid);
        sc[NROWS + tid] = 0.2f * c1;
    }
    __syncthreads();

    const float a = 0.5f * pB[0];                 // tanh-form scale
    const float b = a * (pBEV[0] * BEV[0]);

    const float4* __restrict__ st0 = (const float4*)ST0;
    const float4* __restrict__ w0  = (const float4*)W0;
    const float4* __restrict__ st1 = (const float4*)ST1;
    const float4* __restrict__ w1  = (const float4*)W1;

    float acc = 0.0f;

    // --- 3-stage software pipeline, prefetch distance 2 ---
    TileRegs b0, b1, b2;
    int t = blockIdx.x;                           // GRID << TILES
    load_tile(b0, t, tid, st0, w0, st1, w1, sc);
    bool v1 = (t + GRID < TILES);
    if (v1) load_tile(b1, t + GRID, tid, st0, w0, st1, w1, sc);

    while (true) {
        // phase 0: prefetch t+2G, compute b0 (tile t)
        bool v2 = (t + 2 * GRID < TILES);
        if (v2) load_tile(b2, t + 2 * GRID, tid, st0, w0, st1, w1, sc);
        acc += compute_tile(b0, a, b);
        if (!v1) break;

        // phase 1: prefetch t+3G into b0, compute b1 (tile t+G)
        bool v3 = (t + 3 * GRID < TILES);
        if (v3) load_tile(b0, t + 3 * GRID, tid, st0, w0, st1, w1, sc);
        acc += compute_tile(b1, a, b);
        if (!v2) break;

        // phase 2: prefetch t+4G into b1, compute b2 (tile t+2G)
        bool v4 = (t + 4 * GRID < TILES);
        if (v4) load_tile(b1, t + 4 * GRID, tid, st0, w0, st1, w1, sc);
        acc += compute_tile(b2, a, b);
        if (!v3) break;

        t += 3 * GRID;
        v1 = v4;
    }

    // --- block reduce (fixed tree, deterministic) ---
    for (int off = 16; off > 0; off >>= 1)
        acc += __shfl_down_sync(0xFFFFFFFFu, acc, off);

    __shared__ float sm[BLOCK / 32];
    int lane = tid & 31;
    int wid  = tid >> 5;
    if (lane == 0) sm[wid] = acc;
    __syncthreads();
    if (wid == 0) {
        float bsum = (lane < BLOCK / 32) ? sm[lane] : 0.0f;
        for (int off = 4; off > 0; off >>= 1)
            bsum += __shfl_down_sync(0xFFFFFFFFu, bsum, off);
        if (lane == 0) g_part[blockIdx.x] = bsum;
    }

    // --- last block folds partials (deterministic fixed-order) ---
    __shared__ bool is_last;
    __threadfence();
    if (tid == 0)
        is_last = (atomicAdd(&g_sem, 1u) == GRID - 1);
    __syncthreads();

    if (is_last) {
        __threadfence();
        float a2 = 0.0f;
        for (int i = tid; i < GRID; i += BLOCK)
            a2 += g_part[i];
        for (int off = 16; off > 0; off >>= 1)
            a2 += __shfl_down_sync(0xFFFFFFFFu, a2, off);
        if (lane == 0) sm[wid] = a2;
        __syncthreads();
        if (tid == 0) {
            float s = 0.0f;
            #pragma unroll
            for (int i = 0; i < BLOCK / 32; i++) s += sm[i];
            out[0] = s;
            g_sem  = 0;
        }
    }
}

// Input order: BEV, ST0, Weight0, ST1, Weight1, Problem, probs0..4, pBEV, pB
extern "C" void kernel_launch(void* const* d_in, const int* in_sizes, int n_in,
                              void* d_out, int out_size) {
    const float* BEV    = (const float*)d_in[0];
    const float* ST0    = (const float*)d_in[1];
    const float* W0     = (const float*)d_in[2];
    const float* ST1    = (const float*)d_in[3];
    const float* W1     = (const float*)d_in[4];
    const float* probs0 = (const float*)d_in[6];
    const float* probs1 = (const float*)d_in[7];
    const float* probs2 = (const float*)d_in[8];
    const float* probs3 = (const float*)d_in[9];
    const float* probs4 = (const float*)d_in[10];
    const float* pBEV   = (const float*)d_in[11];
    const float* pB     = (const float*)d_in[12];

    fused_kernel<<<GRID, BLOCK>>>(BEV, ST0, W0, ST1, W1,
                                  probs0, probs1, probs2, probs3, probs4,
                                  pBEV, pB, (float*)d_out);
}